// round 3
// baseline (speedup 1.0000x reference)
#include <cuda_runtime.h>
#include <cstdint>

// Problem constants
#define BATCH 2
#define L_SEQ 2048
#define CDIM  1024
#define HEADS 16
#define HD    64
#define MTOT  (BATCH * L_SEQ)       // 4096
#define THREEC (3 * CDIM)           // 3072
#define INV4  0.3535533905932738f   // 64^-0.25

// ---------------------------------------------------------------------------
// Scratch (device globals; no allocation allowed)
// ---------------------------------------------------------------------------
__device__ __align__(16) float g_qkv[(size_t)MTOT * THREEC];  // 48 MB
__device__ __align__(16) float g_q[(size_t)MTOT * CDIM];      // [B,H,L,D]
__device__ __align__(16) float g_k[(size_t)MTOT * CDIM];
__device__ __align__(16) float g_v[(size_t)MTOT * CDIM];
__device__ __align__(16) float g_att[(size_t)MTOT * CDIM];    // [B,L,H*D]

// ---------------------------------------------------------------------------
// Helpers
// ---------------------------------------------------------------------------
__device__ __forceinline__ uint32_t f2tf32(float f) {
    uint32_t r;
    asm("cvt.rna.tf32.f32 %0, %1;" : "=r"(r) : "f"(f));
    return r;
}

__device__ __forceinline__ void mma_tf32(float* d,
                                         uint32_t a0, uint32_t a1, uint32_t a2, uint32_t a3,
                                         uint32_t b0, uint32_t b1) {
    asm volatile(
        "mma.sync.aligned.m16n8k8.row.col.f32.tf32.tf32.f32 "
        "{%0,%1,%2,%3}, {%4,%5,%6,%7}, {%8,%9}, {%0,%1,%2,%3};\n"
        : "+f"(d[0]), "+f"(d[1]), "+f"(d[2]), "+f"(d[3])
        : "r"(a0), "r"(a1), "r"(a2), "r"(a3), "r"(b0), "r"(b1));
}

// pair-permutation within each 8-col group: maps (t, t+4) -> (2t, 2t+1)
__device__ __forceinline__ int pair_perm(int c) {
    return (c & ~7) | (((c & 3) << 1) | ((c >> 2) & 1));
}

// ---------------------------------------------------------------------------
// TF32 tensor-core GEMM (unchanged from round 2)
// ---------------------------------------------------------------------------
#define AS_STR 17
#define BS_STR 136

__global__ __launch_bounds__(256) void gemm_tf32_kernel(
    const float* __restrict__ A, const float* __restrict__ B,
    float* __restrict__ C, int M, int N, int K)
{
    __shared__ float As[128 * AS_STR];   // [m][k], tf32-rounded
    __shared__ float Bs[16 * BS_STR];    // [k][n], tf32-rounded

    const int tid  = threadIdx.x;
    const int w    = tid >> 5;
    const int lane = tid & 31;
    const int g = lane >> 2;
    const int t = lane & 3;
    const int wm = (w & 1) * 64;
    const int wn = (w >> 1) * 32;
    const int m0 = blockIdx.y * 128;
    const int n0 = blockIdx.x * 128;

    const int a_row = tid >> 1;
    const int a_k   = (tid & 1) * 8;
    const int b_row = tid >> 4;
    const int b_c   = (tid & 15) * 8;

    float acc[4][4][4];
#pragma unroll
    for (int i = 0; i < 4; i++)
#pragma unroll
        for (int j = 0; j < 4; j++)
#pragma unroll
            for (int v = 0; v < 4; v++) acc[i][j][v] = 0.f;

    float4 pa0, pa1, pb0, pb1;
    pa0 = *(const float4*)&A[(size_t)(m0 + a_row) * K + a_k];
    pa1 = *(const float4*)&A[(size_t)(m0 + a_row) * K + a_k + 4];
    pb0 = *(const float4*)&B[(size_t)b_row * N + n0 + b_c];
    pb1 = *(const float4*)&B[(size_t)b_row * N + n0 + b_c + 4];

    {
        float* ap = &As[a_row * AS_STR + a_k];
        ap[0] = __uint_as_float(f2tf32(pa0.x)); ap[1] = __uint_as_float(f2tf32(pa0.y));
        ap[2] = __uint_as_float(f2tf32(pa0.z)); ap[3] = __uint_as_float(f2tf32(pa0.w));
        ap[4] = __uint_as_float(f2tf32(pa1.x)); ap[5] = __uint_as_float(f2tf32(pa1.y));
        ap[6] = __uint_as_float(f2tf32(pa1.z)); ap[7] = __uint_as_float(f2tf32(pa1.w));
        float* bp = &Bs[b_row * BS_STR + b_c];
        bp[0] = __uint_as_float(f2tf32(pb0.x)); bp[1] = __uint_as_float(f2tf32(pb0.y));
        bp[2] = __uint_as_float(f2tf32(pb0.z)); bp[3] = __uint_as_float(f2tf32(pb0.w));
        bp[4] = __uint_as_float(f2tf32(pb1.x)); bp[5] = __uint_as_float(f2tf32(pb1.y));
        bp[6] = __uint_as_float(f2tf32(pb1.z)); bp[7] = __uint_as_float(f2tf32(pb1.w));
    }
    __syncthreads();

    for (int k0 = 0; k0 < K; k0 += 16) {
        const bool has_next = (k0 + 16 < K);
        if (has_next) {
            pa0 = *(const float4*)&A[(size_t)(m0 + a_row) * K + k0 + 16 + a_k];
            pa1 = *(const float4*)&A[(size_t)(m0 + a_row) * K + k0 + 16 + a_k + 4];
            pb0 = *(const float4*)&B[(size_t)(k0 + 16 + b_row) * N + n0 + b_c];
            pb1 = *(const float4*)&B[(size_t)(k0 + 16 + b_row) * N + n0 + b_c + 4];
        }

#pragma unroll
        for (int ks = 0; ks < 2; ks++) {
            uint32_t af[4][4], bf[4][2];
#pragma unroll
            for (int mt = 0; mt < 4; mt++) {
                const float* base = &As[(wm + mt * 16 + g) * AS_STR + ks * 8 + t];
                af[mt][0] = __float_as_uint(base[0]);
                af[mt][1] = __float_as_uint(base[8 * AS_STR]);
                af[mt][2] = __float_as_uint(base[4]);
                af[mt][3] = __float_as_uint(base[8 * AS_STR + 4]);
            }
#pragma unroll
            for (int nt = 0; nt < 4; nt++) {
                const float* base = &Bs[(ks * 8 + t) * BS_STR + wn + nt * 8 + g];
                bf[nt][0] = __float_as_uint(base[0]);
                bf[nt][1] = __float_as_uint(base[4 * BS_STR]);
            }
#pragma unroll
            for (int mt = 0; mt < 4; mt++)
#pragma unroll
                for (int nt = 0; nt < 4; nt++)
                    mma_tf32(acc[mt][nt], af[mt][0], af[mt][1], af[mt][2], af[mt][3],
                             bf[nt][0], bf[nt][1]);
        }
        __syncthreads();

        if (has_next) {
            float* ap = &As[a_row * AS_STR + a_k];
            ap[0] = __uint_as_float(f2tf32(pa0.x)); ap[1] = __uint_as_float(f2tf32(pa0.y));
            ap[2] = __uint_as_float(f2tf32(pa0.z)); ap[3] = __uint_as_float(f2tf32(pa0.w));
            ap[4] = __uint_as_float(f2tf32(pa1.x)); ap[5] = __uint_as_float(f2tf32(pa1.y));
            ap[6] = __uint_as_float(f2tf32(pa1.z)); ap[7] = __uint_as_float(f2tf32(pa1.w));
            float* bp = &Bs[b_row * BS_STR + b_c];
            bp[0] = __uint_as_float(f2tf32(pb0.x)); bp[1] = __uint_as_float(f2tf32(pb0.y));
            bp[2] = __uint_as_float(f2tf32(pb0.z)); bp[3] = __uint_as_float(f2tf32(pb0.w));
            bp[4] = __uint_as_float(f2tf32(pb1.x)); bp[5] = __uint_as_float(f2tf32(pb1.y));
            bp[6] = __uint_as_float(f2tf32(pb1.z)); bp[7] = __uint_as_float(f2tf32(pb1.w));
            __syncthreads();
        }
    }

#pragma unroll
    for (int mt = 0; mt < 4; mt++) {
        const int row = m0 + wm + mt * 16 + g;
#pragma unroll
        for (int nt = 0; nt < 4; nt++) {
            const int col = n0 + wn + nt * 8 + 2 * t;
            float2 v0 = make_float2(acc[mt][nt][0], acc[mt][nt][1]);
            float2 v1 = make_float2(acc[mt][nt][2], acc[mt][nt][3]);
            *(float2*)&C[(size_t)row * N + col] = v0;
            *(float2*)&C[(size_t)(row + 8) * N + col] = v1;
        }
    }
}

// ---------------------------------------------------------------------------
// LayerNorm(q,k)*D^-0.25 + split; outputs tf32-rounded (unchanged)
// ---------------------------------------------------------------------------
__global__ __launch_bounds__(256) void ln_split_kernel(
    const float* __restrict__ qkv,
    const float* __restrict__ q_scale, const float* __restrict__ q_bias,
    const float* __restrict__ k_scale, const float* __restrict__ k_bias,
    float* __restrict__ q_t, float* __restrict__ k_t, float* __restrict__ v_t)
{
    const int wid  = (blockIdx.x * blockDim.x + threadIdx.x) >> 5;
    const int lane = threadIdx.x & 31;
    const int h = wid & (HEADS - 1);
    const int m = wid >> 4;
    const int b = m >> 11;
    const int l = m & (L_SEQ - 1);

    const float* row = qkv + (size_t)m * THREEC;
    const size_t obase = (((size_t)(b * HEADS + h)) * L_SEQ + l) * HD;

    {
        float x0 = row[h * HD + lane];
        float x1 = row[h * HD + lane + 32];
        float s = x0 + x1;
#pragma unroll
        for (int o = 16; o > 0; o >>= 1) s += __shfl_xor_sync(0xffffffffu, s, o);
        float mu = s * (1.f / HD);
        float d0 = x0 - mu, d1 = x1 - mu;
        float vs = d0 * d0 + d1 * d1;
#pragma unroll
        for (int o = 16; o > 0; o >>= 1) vs += __shfl_xor_sync(0xffffffffu, vs, o);
        float rstd = rsqrtf(vs * (1.f / HD) + 1e-6f);
        q_t[obase + lane] =
            __uint_as_float(f2tf32((d0 * rstd * q_scale[lane] + q_bias[lane]) * INV4));
        q_t[obase + lane + 32] =
            __uint_as_float(f2tf32((d1 * rstd * q_scale[lane + 32] + q_bias[lane + 32]) * INV4));
    }
    {
        float x0 = row[CDIM + h * HD + lane];
        float x1 = row[CDIM + h * HD + lane + 32];
        float s = x0 + x1;
#pragma unroll
        for (int o = 16; o > 0; o >>= 1) s += __shfl_xor_sync(0xffffffffu, s, o);
        float mu = s * (1.f / HD);
        float d0 = x0 - mu, d1 = x1 - mu;
        float vs = d0 * d0 + d1 * d1;
#pragma unroll
        for (int o = 16; o > 0; o >>= 1) vs += __shfl_xor_sync(0xffffffffu, vs, o);
        float rstd = rsqrtf(vs * (1.f / HD) + 1e-6f);
        k_t[obase + lane] =
            __uint_as_float(f2tf32((d0 * rstd * k_scale[lane] + k_bias[lane]) * INV4));
        k_t[obase + lane + 32] =
            __uint_as_float(f2tf32((d1 * rstd * k_scale[lane + 32] + k_bias[lane + 32]) * INV4));
    }
    v_t[obase + lane]      = __uint_as_float(f2tf32(row[2 * CDIM + h * HD + lane]));
    v_t[obase + lane + 32] = __uint_as_float(f2tf32(row[2 * CDIM + h * HD + lane + 32]));
}

// ---------------------------------------------------------------------------
// Flash attention, tf32 tensor cores, round 3:
//  - Q resident in SMEM (perm layout, stride 72) -> no register spills
//  - K in SMEM [key][perm(d)] stride 72 (as round 2)
//  - V in SMEM TRANSPOSED [d][perm(key)] stride 72, key-major store lanes
//    -> PV B-frags are single conflict-free LDS.64
// Dynamic smem: (128 + 64 + 64) * 72 * 4 = 73,728 B
// ---------------------------------------------------------------------------
#define QS_STR 72
#define KS_STR 72
#define VT_STR 72
#define ATTN_SMEM_BYTES ((128 * QS_STR + 64 * KS_STR + 64 * VT_STR) * 4)

__global__ __launch_bounds__(256, 2) void attn_mma_kernel(
    const float* __restrict__ q_t, const float* __restrict__ k_t,
    const float* __restrict__ v_t, float* __restrict__ att)
{
    extern __shared__ float sm[];
    float* Qs = sm;                              // 128 x 72  [qrow][perm(d)]
    float* Ks = sm + 128 * QS_STR;               // 64 x 72   [key][perm(d)]
    float* Vt = sm + 128 * QS_STR + 64 * KS_STR; // 64 x 72   [d][perm(key)]

    const int tid  = threadIdx.x;
    const int w    = tid >> 5;
    const int lane = tid & 31;
    const int g = lane >> 2;
    const int t = lane & 3;
    const int bh = blockIdx.y;          // b*16 + h
    const int q0 = blockIdx.x * 128;

    const float* Qp = q_t + (size_t)bh * L_SEQ * HD;
    const float* Kp = k_t + (size_t)bh * L_SEQ * HD;
    const float* Vp = v_t + (size_t)bh * L_SEQ * HD;

    // Load Q tile once: 128 rows x 64 d, perm layout
#pragma unroll
    for (int i = 0; i < 8; i++) {
        int idx = tid + i * 256;
        int r  = idx >> 4;
        int d4 = (idx & 15) << 2;
        float4 qv = *(const float4*)&Qp[(size_t)(q0 + r) * HD + d4];
        Qs[r * QS_STR + pair_perm(d4 + 0)] = qv.x;
        Qs[r * QS_STR + pair_perm(d4 + 1)] = qv.y;
        Qs[r * QS_STR + pair_perm(d4 + 2)] = qv.z;
        Qs[r * QS_STR + pair_perm(d4 + 3)] = qv.w;
    }

    float o[8][4];
#pragma unroll
    for (int nn = 0; nn < 8; nn++)
#pragma unroll
        for (int v = 0; v < 4; v++) o[nn][v] = 0.f;
    float mrow0 = -1e30f, mrow1 = -1e30f;
    float lrow0 = 0.f,    lrow1 = 0.f;

    const int qr0 = w * 16;             // warp's q-row base within CTA tile

    for (int kt = 0; kt < L_SEQ; kt += 64) {
        __syncthreads();
        // K tile: [64 key][64 d] -> Ks[key][perm(d)]
#pragma unroll
        for (int i = 0; i < 4; i++) {
            int idx = tid + i * 256;
            int key = idx >> 4;
            int d4  = (idx & 15) << 2;
            float4 kv = *(const float4*)&Kp[(size_t)(kt + key) * HD + d4];
            Ks[key * KS_STR + pair_perm(d4 + 0)] = kv.x;
            Ks[key * KS_STR + pair_perm(d4 + 1)] = kv.y;
            Ks[key * KS_STR + pair_perm(d4 + 2)] = kv.z;
            Ks[key * KS_STR + pair_perm(d4 + 3)] = kv.w;
        }
        // V tile transposed: Vt[d][perm(key)], key-major lanes (conflict-free STS)
#pragma unroll
        for (int i = 0; i < 4; i++) {
            int idx = tid + i * 256;
            int key = idx & 63;
            int dg  = (idx >> 6) << 2;   // 0,4,...,60
            float4 vv = *(const float4*)&Vp[(size_t)(kt + key) * HD + dg];
            int pk = pair_perm(key);
            Vt[(dg + 0) * VT_STR + pk] = vv.x;
            Vt[(dg + 1) * VT_STR + pk] = vv.y;
            Vt[(dg + 2) * VT_STR + pk] = vv.z;
            Vt[(dg + 3) * VT_STR + pk] = vv.w;
        }
        __syncthreads();

        // S = Q K^T : kk outer (Q frag regs transient), nn inner
        float s[8][4];
#pragma unroll
        for (int nn = 0; nn < 8; nn++)
#pragma unroll
            for (int v = 0; v < 4; v++) s[nn][v] = 0.f;

#pragma unroll
        for (int kk = 0; kk < 8; kk++) {
            float2 qa02 = *(const float2*)&Qs[(qr0 + g)     * QS_STR + kk * 8 + 2 * t];
            float2 qa13 = *(const float2*)&Qs[(qr0 + g + 8) * QS_STR + kk * 8 + 2 * t];
            uint32_t a0 = __float_as_uint(qa02.x);
            uint32_t a1 = __float_as_uint(qa13.x);
            uint32_t a2 = __float_as_uint(qa02.y);
            uint32_t a3 = __float_as_uint(qa13.y);
#pragma unroll
            for (int nn = 0; nn < 8; nn++) {
                float2 b = *(const float2*)&Ks[(nn * 8 + g) * KS_STR + kk * 8 + 2 * t];
                mma_tf32(s[nn], a0, a1, a2, a3,
                         __float_as_uint(b.x), __float_as_uint(b.y));
            }
        }

        // online softmax (rows g, g+8; quad reductions)
        float mx0 = -1e30f, mx1 = -1e30f;
#pragma unroll
        for (int nn = 0; nn < 8; nn++) {
            mx0 = fmaxf(mx0, fmaxf(s[nn][0], s[nn][1]));
            mx1 = fmaxf(mx1, fmaxf(s[nn][2], s[nn][3]));
        }
        mx0 = fmaxf(mx0, __shfl_xor_sync(0xffffffffu, mx0, 1));
        mx0 = fmaxf(mx0, __shfl_xor_sync(0xffffffffu, mx0, 2));
        mx1 = fmaxf(mx1, __shfl_xor_sync(0xffffffffu, mx1, 1));
        mx1 = fmaxf(mx1, __shfl_xor_sync(0xffffffffu, mx1, 2));

        float mn0 = fmaxf(mrow0, mx0);
        float mn1 = fmaxf(mrow1, mx1);
        float alpha0 = __expf(mrow0 - mn0);
        float alpha1 = __expf(mrow1 - mn1);
        mrow0 = mn0; mrow1 = mn1;

        float rs0 = 0.f, rs1 = 0.f;
#pragma unroll
        for (int nn = 0; nn < 8; nn++) {
            float p0 = __expf(s[nn][0] - mn0);
            float p1 = __expf(s[nn][1] - mn0);
            float p2 = __expf(s[nn][2] - mn1);
            float p3 = __expf(s[nn][3] - mn1);
            rs0 += p0 + p1;
            rs1 += p2 + p3;
            s[nn][0] = __uint_as_float(f2tf32(p0));
            s[nn][1] = __uint_as_float(f2tf32(p1));
            s[nn][2] = __uint_as_float(f2tf32(p2));
            s[nn][3] = __uint_as_float(f2tf32(p3));
        }
        rs0 += __shfl_xor_sync(0xffffffffu, rs0, 1);
        rs0 += __shfl_xor_sync(0xffffffffu, rs0, 2);
        rs1 += __shfl_xor_sync(0xffffffffu, rs1, 1);
        rs1 += __shfl_xor_sync(0xffffffffu, rs1, 2);
        lrow0 = lrow0 * alpha0 + rs0;
        lrow1 = lrow1 * alpha1 + rs1;

#pragma unroll
        for (int nn = 0; nn < 8; nn++) {
            o[nn][0] *= alpha0; o[nn][1] *= alpha0;
            o[nn][2] *= alpha1; o[nn][3] *= alpha1;
        }

        // O += P V : shuffle-convert P C-frags -> A-frags, V B-frags via LDS.64
        const int srcA = (lane & ~3) | (t >> 1);
        const int srcB = srcA + 2;
#pragma unroll
        for (int kk = 0; kk < 8; kk++) {
            float c0 = s[kk][0], c1 = s[kk][1], c2 = s[kk][2], c3 = s[kk][3];
            float e0  = __shfl_sync(0xffffffffu, c0, srcA);
            float o0_ = __shfl_sync(0xffffffffu, c1, srcA);
            float e0b = __shfl_sync(0xffffffffu, c0, srcB);
            float o0b = __shfl_sync(0xffffffffu, c1, srcB);
            float e1  = __shfl_sync(0xffffffffu, c2, srcA);
            float o1_ = __shfl_sync(0xffffffffu, c3, srcA);
            float e1b = __shfl_sync(0xffffffffu, c2, srcB);
            float o1b = __shfl_sync(0xffffffffu, c3, srcB);
            uint32_t a0 = __float_as_uint((t & 1) ? o0_ : e0);
            uint32_t a1 = __float_as_uint((t & 1) ? o1_ : e1);
            uint32_t a2 = __float_as_uint((t & 1) ? o0b : e0b);
            uint32_t a3 = __float_as_uint((t & 1) ? o1b : e1b);
#pragma unroll
            for (int nn = 0; nn < 8; nn++) {
                float2 b = *(const float2*)&Vt[(nn * 8 + g) * VT_STR + kk * 8 + 2 * t];
                mma_tf32(o[nn], a0, a1, a2, a3,
                         __float_as_uint(b.x), __float_as_uint(b.y));
            }
        }
    }

    // finalize + store to [B, L, H*D]
    const int b_ = bh >> 4;
    const int h  = bh & (HEADS - 1);
    const float inv0 = 1.f / lrow0;
    const float inv1 = 1.f / lrow1;
    const int qrow = q0 + qr0;
    const size_t base0 = ((size_t)b_ * L_SEQ + qrow + g)     * CDIM + h * HD;
    const size_t base1 = ((size_t)b_ * L_SEQ + qrow + g + 8) * CDIM + h * HD;
#pragma unroll
    for (int nn = 0; nn < 8; nn++) {
        *(float2*)&att[base0 + nn * 8 + 2 * t] = make_float2(o[nn][0] * inv0, o[nn][1] * inv0);
        *(float2*)&att[base1 + nn * 8 + 2 * t] = make_float2(o[nn][2] * inv1, o[nn][3] * inv1);
    }
}

// ---------------------------------------------------------------------------
// Host launch
// ---------------------------------------------------------------------------
extern "C" void kernel_launch(void* const* d_in, const int* in_sizes, int n_in,
                              void* d_out, int out_size)
{
    const float* x       = (const float*)d_in[0];
    const float* w_qkv   = (const float*)d_in[1];
    const float* w_out   = (const float*)d_in[2];
    const float* q_scale = (const float*)d_in[3];
    const float* q_bias  = (const float*)d_in[4];
    const float* k_scale = (const float*)d_in[5];
    const float* k_bias  = (const float*)d_in[6];
    float* out = (float*)d_out;

    void *p_qkv, *p_q, *p_k, *p_v, *p_att;
    cudaGetSymbolAddress(&p_qkv, g_qkv);
    cudaGetSymbolAddress(&p_q, g_q);
    cudaGetSymbolAddress(&p_k, g_k);
    cudaGetSymbolAddress(&p_v, g_v);
    cudaGetSymbolAddress(&p_att, g_att);

    // 1) QKV projection
    gemm_tf32_kernel<<<dim3(THREEC / 128, MTOT / 128), 256>>>(
        x, w_qkv, (float*)p_qkv, MTOT, THREEC, CDIM);

    // 2) QK LayerNorm + head split
    ln_split_kernel<<<(MTOT * HEADS) / 8, 256>>>(
        (const float*)p_qkv, q_scale, q_bias, k_scale, k_bias,
        (float*)p_q, (float*)p_k, (float*)p_v);

    // 3) Flash attention (tensor cores, Q/K/V in smem)
    cudaFuncSetAttribute(attn_mma_kernel, cudaFuncAttributeMaxDynamicSharedMemorySize,
                         ATTN_SMEM_BYTES);
    attn_mma_kernel<<<dim3(L_SEQ / 128, BATCH * HEADS), 256, ATTN_SMEM_BYTES>>>(
        (const float*)p_q, (const float*)p_k, (const float*)p_v, (float*)p_att);

    // 4) Output projection
    gemm_tf32_kernel<<<dim3(CDIM / 128, MTOT / 128), 256>>>(
        (const float*)p_att, w_out, out, MTOT, CDIM, CDIM);
}

// round 4
// speedup vs baseline: 1.0456x; 1.0456x over previous
#include <cuda_runtime.h>
#include <cstdint>

// Problem constants
#define BATCH 2
#define L_SEQ 2048
#define CDIM  1024
#define HEADS 16
#define HD    64
#define MTOT  (BATCH * L_SEQ)       // 4096
#define THREEC (3 * CDIM)           // 3072
#define INV4  0.3535533905932738f   // 64^-0.25

// ---------------------------------------------------------------------------
// Scratch (device globals; no allocation allowed)
// ---------------------------------------------------------------------------
__device__ __align__(16) float g_qkv[(size_t)MTOT * THREEC];  // 48 MB
__device__ __align__(16) float g_q[(size_t)MTOT * CDIM];      // [B,H,L,D]
__device__ __align__(16) float g_k[(size_t)MTOT * CDIM];
__device__ __align__(16) float g_v[(size_t)MTOT * CDIM];
__device__ __align__(16) float g_att[(size_t)MTOT * CDIM];    // [B,L,H*D], tf32-rounded
__device__ __align__(16) float g_xr[(size_t)MTOT * CDIM];     // x, tf32-rounded
__device__ __align__(16) float g_wr[(size_t)CDIM * THREEC];   // w_qkv, tf32-rounded
__device__ __align__(16) float g_wor[(size_t)CDIM * CDIM];    // w_out, tf32-rounded

// ---------------------------------------------------------------------------
// Helpers
// ---------------------------------------------------------------------------
__device__ __forceinline__ uint32_t f2tf32(float f) {
    uint32_t r;
    asm("cvt.rna.tf32.f32 %0, %1;" : "=r"(r) : "f"(f));
    return r;
}

__device__ __forceinline__ void mma_tf32(float* d,
                                         uint32_t a0, uint32_t a1, uint32_t a2, uint32_t a3,
                                         uint32_t b0, uint32_t b1) {
    asm volatile(
        "mma.sync.aligned.m16n8k8.row.col.f32.tf32.tf32.f32 "
        "{%0,%1,%2,%3}, {%4,%5,%6,%7}, {%8,%9}, {%0,%1,%2,%3};\n"
        : "+f"(d[0]), "+f"(d[1]), "+f"(d[2]), "+f"(d[3])
        : "r"(a0), "r"(a1), "r"(a2), "r"(a3), "r"(b0), "r"(b1));
}

__device__ __forceinline__ void cp16(void* smem, const void* gmem) {
    uint32_t s = (uint32_t)__cvta_generic_to_shared(smem);
    asm volatile("cp.async.ca.shared.global [%0], [%1], 16;" :: "r"(s), "l"(gmem));
}
__device__ __forceinline__ void cp_commit() {
    asm volatile("cp.async.commit_group;");
}
__device__ __forceinline__ void cp_wait0() {
    asm volatile("cp.async.wait_group 0;");
}

// pair-permutation within each 8-col group: maps (t, t+4) -> (2t, 2t+1)
__device__ __forceinline__ int pair_perm(int c) {
    return (c & ~7) | (((c & 3) << 1) | ((c >> 2) & 1));
}

// ---------------------------------------------------------------------------
// tf32 pre-rounding pass (hoists cvt out of GEMM hot loops)
// ---------------------------------------------------------------------------
__global__ __launch_bounds__(256) void round_tf32_kernel(
    const float* __restrict__ src, float* __restrict__ dst, int n4)
{
    int i = blockIdx.x * blockDim.x + threadIdx.x;
    if (i < n4) {
        float4 v = ((const float4*)src)[i];
        v.x = __uint_as_float(f2tf32(v.x));
        v.y = __uint_as_float(f2tf32(v.y));
        v.z = __uint_as_float(f2tf32(v.z));
        v.w = __uint_as_float(f2tf32(v.w));
        ((float4*)dst)[i] = v;
    }
}

// ---------------------------------------------------------------------------
// Double-buffered cp.async TF32 GEMM: C[M,N] = A[M,K]*B[K,N]
// BM=BN=128, BK=32, 256 threads (8 warps, each 64x32 via 4x4 m16n8 tiles)
// Inputs must be pre-rounded to tf32.
// Dyn smem: 2*(128*36 + 32*136)*4 = 71,680 B
// ---------------------------------------------------------------------------
#define GAS_STR 36     // As row stride (floats): 32 data + 4 pad (16B aligned)
#define GBS_STR 136    // Bs row stride (floats): 128 data + 8 pad (16B aligned)
#define A_STAGE (128 * GAS_STR)
#define B_STAGE (32 * GBS_STR)
#define GEMM_SMEM_BYTES ((2 * (A_STAGE + B_STAGE)) * 4)

__global__ __launch_bounds__(256, 2) void gemm_db_kernel(
    const float* __restrict__ A, const float* __restrict__ B,
    float* __restrict__ C, int M, int N, int K)
{
    extern __shared__ float dsm[];
    float* As = dsm;                 // [2][128][GAS_STR]
    float* Bs = dsm + 2 * A_STAGE;   // [2][32][GBS_STR]

    const int tid  = threadIdx.x;
    const int w    = tid >> 5;
    const int lane = tid & 31;
    const int g = lane >> 2;
    const int t = lane & 3;
    const int wm = (w & 1) * 64;
    const int wn = (w >> 1) * 32;
    const int m0 = blockIdx.y * 128;
    const int n0 = blockIdx.x * 128;

    // copy assignments: A rows 0..127, 16-float halves; B rows 0..31, 16-float chunks
    const int a_row  = tid >> 1;
    const int a_off  = (tid & 1) * 16;
    const int b_row  = tid >> 3;
    const int b_off  = (tid & 7) * 16;

    const float* gA = &A[(size_t)(m0 + a_row) * K + a_off];
    const float* gB = &B[(size_t)b_row * N + n0 + b_off];

    float acc[4][4][4];
#pragma unroll
    for (int i = 0; i < 4; i++)
#pragma unroll
        for (int j = 0; j < 4; j++)
#pragma unroll
            for (int v = 0; v < 4; v++) acc[i][j][v] = 0.f;

    // prologue: stage 0
    {
        float* sa = &As[a_row * GAS_STR + a_off];
        cp16(sa,      gA);
        cp16(sa + 4,  gA + 4);
        cp16(sa + 8,  gA + 8);
        cp16(sa + 12, gA + 12);
        float* sb = &Bs[b_row * GBS_STR + b_off];
        cp16(sb,      gB);
        cp16(sb + 4,  gB + 4);
        cp16(sb + 8,  gB + 8);
        cp16(sb + 12, gB + 12);
        cp_commit();
    }

    int buf = 0;
    for (int k0 = 0; k0 < K; k0 += 32) {
        cp_wait0();
        __syncthreads();

        if (k0 + 32 < K) {
            const int nb = buf ^ 1;
            float* sa = &As[nb * A_STAGE + a_row * GAS_STR + a_off];
            const float* ga = gA + k0 + 32;
            cp16(sa,      ga);
            cp16(sa + 4,  ga + 4);
            cp16(sa + 8,  ga + 8);
            cp16(sa + 12, ga + 12);
            float* sb = &Bs[nb * B_STAGE + b_row * GBS_STR + b_off];
            const float* gb = gB + (size_t)(k0 + 32) * N;
            cp16(sb,      gb);
            cp16(sb + 4,  gb + 4);
            cp16(sb + 8,  gb + 8);
            cp16(sb + 12, gb + 12);
            cp_commit();
        }

        const float* as = &As[buf * A_STAGE];
        const float* bs = &Bs[buf * B_STAGE];
#pragma unroll
        for (int ks = 0; ks < 4; ks++) {
            uint32_t af[4][4], bf[4][2];
#pragma unroll
            for (int mt = 0; mt < 4; mt++) {
                const float* base = &as[(wm + mt * 16 + g) * GAS_STR + ks * 8 + t];
                af[mt][0] = __float_as_uint(base[0]);
                af[mt][1] = __float_as_uint(base[8 * GAS_STR]);
                af[mt][2] = __float_as_uint(base[4]);
                af[mt][3] = __float_as_uint(base[8 * GAS_STR + 4]);
            }
#pragma unroll
            for (int nt = 0; nt < 4; nt++) {
                const float* base = &bs[(ks * 8 + t) * GBS_STR + wn + nt * 8 + g];
                bf[nt][0] = __float_as_uint(base[0]);
                bf[nt][1] = __float_as_uint(base[4 * GBS_STR]);
            }
#pragma unroll
            for (int mt = 0; mt < 4; mt++)
#pragma unroll
                for (int nt = 0; nt < 4; nt++)
                    mma_tf32(acc[mt][nt], af[mt][0], af[mt][1], af[mt][2], af[mt][3],
                             bf[nt][0], bf[nt][1]);
        }
        buf ^= 1;
    }

    // epilogue
#pragma unroll
    for (int mt = 0; mt < 4; mt++) {
        const int row = m0 + wm + mt * 16 + g;
#pragma unroll
        for (int nt = 0; nt < 4; nt++) {
            const int col = n0 + wn + nt * 8 + 2 * t;
            float2 v0 = make_float2(acc[mt][nt][0], acc[mt][nt][1]);
            float2 v1 = make_float2(acc[mt][nt][2], acc[mt][nt][3]);
            *(float2*)&C[(size_t)row * N + col] = v0;
            *(float2*)&C[(size_t)(row + 8) * N + col] = v1;
        }
    }
}

// ---------------------------------------------------------------------------
// LayerNorm(q,k)*D^-0.25 + split; outputs tf32-rounded (unchanged)
// ---------------------------------------------------------------------------
__global__ __launch_bounds__(256) void ln_split_kernel(
    const float* __restrict__ qkv,
    const float* __restrict__ q_scale, const float* __restrict__ q_bias,
    const float* __restrict__ k_scale, const float* __restrict__ k_bias,
    float* __restrict__ q_t, float* __restrict__ k_t, float* __restrict__ v_t)
{
    const int wid  = (blockIdx.x * blockDim.x + threadIdx.x) >> 5;
    const int lane = threadIdx.x & 31;
    const int h = wid & (HEADS - 1);
    const int m = wid >> 4;
    const int b = m >> 11;
    const int l = m & (L_SEQ - 1);

    const float* row = qkv + (size_t)m * THREEC;
    const size_t obase = (((size_t)(b * HEADS + h)) * L_SEQ + l) * HD;

    {
        float x0 = row[h * HD + lane];
        float x1 = row[h * HD + lane + 32];
        float s = x0 + x1;
#pragma unroll
        for (int o = 16; o > 0; o >>= 1) s += __shfl_xor_sync(0xffffffffu, s, o);
        float mu = s * (1.f / HD);
        float d0 = x0 - mu, d1 = x1 - mu;
        float vs = d0 * d0 + d1 * d1;
#pragma unroll
        for (int o = 16; o > 0; o >>= 1) vs += __shfl_xor_sync(0xffffffffu, vs, o);
        float rstd = rsqrtf(vs * (1.f / HD) + 1e-6f);
        q_t[obase + lane] =
            __uint_as_float(f2tf32((d0 * rstd * q_scale[lane] + q_bias[lane]) * INV4));
        q_t[obase + lane + 32] =
            __uint_as_float(f2tf32((d1 * rstd * q_scale[lane + 32] + q_bias[lane + 32]) * INV4));
    }
    {
        float x0 = row[CDIM + h * HD + lane];
        float x1 = row[CDIM + h * HD + lane + 32];
        float s = x0 + x1;
#pragma unroll
        for (int o = 16; o > 0; o >>= 1) s += __shfl_xor_sync(0xffffffffu, s, o);
        float mu = s * (1.f / HD);
        float d0 = x0 - mu, d1 = x1 - mu;
        float vs = d0 * d0 + d1 * d1;
#pragma unroll
        for (int o = 16; o > 0; o >>= 1) vs += __shfl_xor_sync(0xffffffffu, vs, o);
        float rstd = rsqrtf(vs * (1.f / HD) + 1e-6f);
        k_t[obase + lane] =
            __uint_as_float(f2tf32((d0 * rstd * k_scale[lane] + k_bias[lane]) * INV4));
        k_t[obase + lane + 32] =
            __uint_as_float(f2tf32((d1 * rstd * k_scale[lane + 32] + k_bias[lane + 32]) * INV4));
    }
    v_t[obase + lane]      = __uint_as_float(f2tf32(row[2 * CDIM + h * HD + lane]));
    v_t[obase + lane + 32] = __uint_as_float(f2tf32(row[2 * CDIM + h * HD + lane + 32]));
}

// ---------------------------------------------------------------------------
// Flash attention (tf32 tensor cores) — round-3 structure, epilogue now
// rounds output to tf32 so gemm2 needs no cvt.
// ---------------------------------------------------------------------------
#define QS_STR 72
#define KS_STR 72
#define VT_STR 72
#define ATTN_SMEM_BYTES ((128 * QS_STR + 64 * KS_STR + 64 * VT_STR) * 4)

__global__ __launch_bounds__(256, 2) void attn_mma_kernel(
    const float* __restrict__ q_t, const float* __restrict__ k_t,
    const float* __restrict__ v_t, float* __restrict__ att)
{
    extern __shared__ float sm[];
    float* Qs = sm;                              // 128 x 72  [qrow][perm(d)]
    float* Ks = sm + 128 * QS_STR;               // 64 x 72   [key][perm(d)]
    float* Vt = sm + 128 * QS_STR + 64 * KS_STR; // 64 x 72   [d][perm(key)]

    const int tid  = threadIdx.x;
    const int w    = tid >> 5;
    const int lane = tid & 31;
    const int g = lane >> 2;
    const int t = lane & 3;
    const int bh = blockIdx.y;          // b*16 + h
    const int q0 = blockIdx.x * 128;

    const float* Qp = q_t + (size_t)bh * L_SEQ * HD;
    const float* Kp = k_t + (size_t)bh * L_SEQ * HD;
    const float* Vp = v_t + (size_t)bh * L_SEQ * HD;

#pragma unroll
    for (int i = 0; i < 8; i++) {
        int idx = tid + i * 256;
        int r  = idx >> 4;
        int d4 = (idx & 15) << 2;
        float4 qv = *(const float4*)&Qp[(size_t)(q0 + r) * HD + d4];
        Qs[r * QS_STR + pair_perm(d4 + 0)] = qv.x;
        Qs[r * QS_STR + pair_perm(d4 + 1)] = qv.y;
        Qs[r * QS_STR + pair_perm(d4 + 2)] = qv.z;
        Qs[r * QS_STR + pair_perm(d4 + 3)] = qv.w;
    }

    float o[8][4];
#pragma unroll
    for (int nn = 0; nn < 8; nn++)
#pragma unroll
        for (int v = 0; v < 4; v++) o[nn][v] = 0.f;
    float mrow0 = -1e30f, mrow1 = -1e30f;
    float lrow0 = 0.f,    lrow1 = 0.f;

    const int qr0 = w * 16;

    for (int kt = 0; kt < L_SEQ; kt += 64) {
        __syncthreads();
#pragma unroll
        for (int i = 0; i < 4; i++) {
            int idx = tid + i * 256;
            int key = idx >> 4;
            int d4  = (idx & 15) << 2;
            float4 kv = *(const float4*)&Kp[(size_t)(kt + key) * HD + d4];
            Ks[key * KS_STR + pair_perm(d4 + 0)] = kv.x;
            Ks[key * KS_STR + pair_perm(d4 + 1)] = kv.y;
            Ks[key * KS_STR + pair_perm(d4 + 2)] = kv.z;
            Ks[key * KS_STR + pair_perm(d4 + 3)] = kv.w;
        }
#pragma unroll
        for (int i = 0; i < 4; i++) {
            int idx = tid + i * 256;
            int key = idx & 63;
            int dg  = (idx >> 6) << 2;
            float4 vv = *(const float4*)&Vp[(size_t)(kt + key) * HD + dg];
            int pk = pair_perm(key);
            Vt[(dg + 0) * VT_STR + pk] = vv.x;
            Vt[(dg + 1) * VT_STR + pk] = vv.y;
            Vt[(dg + 2) * VT_STR + pk] = vv.z;
            Vt[(dg + 3) * VT_STR + pk] = vv.w;
        }
        __syncthreads();

        float s[8][4];
#pragma unroll
        for (int nn = 0; nn < 8; nn++)
#pragma unroll
            for (int v = 0; v < 4; v++) s[nn][v] = 0.f;

#pragma unroll
        for (int kk = 0; kk < 8; kk++) {
            float2 qa02 = *(const float2*)&Qs[(qr0 + g)     * QS_STR + kk * 8 + 2 * t];
            float2 qa13 = *(const float2*)&Qs[(qr0 + g + 8) * QS_STR + kk * 8 + 2 * t];
            uint32_t a0 = __float_as_uint(qa02.x);
            uint32_t a1 = __float_as_uint(qa13.x);
            uint32_t a2 = __float_as_uint(qa02.y);
            uint32_t a3 = __float_as_uint(qa13.y);
#pragma unroll
            for (int nn = 0; nn < 8; nn++) {
                float2 b = *(const float2*)&Ks[(nn * 8 + g) * KS_STR + kk * 8 + 2 * t];
                mma_tf32(s[nn], a0, a1, a2, a3,
                         __float_as_uint(b.x), __float_as_uint(b.y));
            }
        }

        float mx0 = -1e30f, mx1 = -1e30f;
#pragma unroll
        for (int nn = 0; nn < 8; nn++) {
            mx0 = fmaxf(mx0, fmaxf(s[nn][0], s[nn][1]));
            mx1 = fmaxf(mx1, fmaxf(s[nn][2], s[nn][3]));
        }
        mx0 = fmaxf(mx0, __shfl_xor_sync(0xffffffffu, mx0, 1));
        mx0 = fmaxf(mx0, __shfl_xor_sync(0xffffffffu, mx0, 2));
        mx1 = fmaxf(mx1, __shfl_xor_sync(0xffffffffu, mx1, 1));
        mx1 = fmaxf(mx1, __shfl_xor_sync(0xffffffffu, mx1, 2));

        float mn0 = fmaxf(mrow0, mx0);
        float mn1 = fmaxf(mrow1, mx1);
        float alpha0 = __expf(mrow0 - mn0);
        float alpha1 = __expf(mrow1 - mn1);
        mrow0 = mn0; mrow1 = mn1;

        float rs0 = 0.f, rs1 = 0.f;
#pragma unroll
        for (int nn = 0; nn < 8; nn++) {
            float p0 = __expf(s[nn][0] - mn0);
            float p1 = __expf(s[nn][1] - mn0);
            float p2 = __expf(s[nn][2] - mn1);
            float p3 = __expf(s[nn][3] - mn1);
            rs0 += p0 + p1;
            rs1 += p2 + p3;
            s[nn][0] = __uint_as_float(f2tf32(p0));
            s[nn][1] = __uint_as_float(f2tf32(p1));
            s[nn][2] = __uint_as_float(f2tf32(p2));
            s[nn][3] = __uint_as_float(f2tf32(p3));
        }
        rs0 += __shfl_xor_sync(0xffffffffu, rs0, 1);
        rs0 += __shfl_xor_sync(0xffffffffu, rs0, 2);
        rs1 += __shfl_xor_sync(0xffffffffu, rs1, 1);
        rs1 += __shfl_xor_sync(0xffffffffu, rs1, 2);
        lrow0 = lrow0 * alpha0 + rs0;
        lrow1 = lrow1 * alpha1 + rs1;

#pragma unroll
        for (int nn = 0; nn < 8; nn++) {
            o[nn][0] *= alpha0; o[nn][1] *= alpha0;
            o[nn][2] *= alpha1; o[nn][3] *= alpha1;
        }

        const int srcA = (lane & ~3) | (t >> 1);
        const int srcB = srcA + 2;
#pragma unroll
        for (int kk = 0; kk < 8; kk++) {
            float c0 = s[kk][0], c1 = s[kk][1], c2 = s[kk][2], c3 = s[kk][3];
            float e0  = __shfl_sync(0xffffffffu, c0, srcA);
            float o0_ = __shfl_sync(0xffffffffu, c1, srcA);
            float e0b = __shfl_sync(0xffffffffu, c0, srcB);
            float o0b = __shfl_sync(0xffffffffu, c1, srcB);
            float e1  = __shfl_sync(0xffffffffu, c2, srcA);
            float o1_ = __shfl_sync(0xffffffffu, c3, srcA);
            float e1b = __shfl_sync(0xffffffffu, c2, srcB);
            float o1b = __shfl_sync(0xffffffffu, c3, srcB);
            uint32_t a0 = __float_as_uint((t & 1) ? o0_ : e0);
            uint32_t a1 = __float_as_uint((t & 1) ? o1_ : e1);
            uint32_t a2 = __float_as_uint((t & 1) ? o0b : e0b);
            uint32_t a3 = __float_as_uint((t & 1) ? o1b : e1b);
#pragma unroll
            for (int nn = 0; nn < 8; nn++) {
                float2 b = *(const float2*)&Vt[(nn * 8 + g) * VT_STR + kk * 8 + 2 * t];
                mma_tf32(o[nn], a0, a1, a2, a3,
                         __float_as_uint(b.x), __float_as_uint(b.y));
            }
        }
    }

    // finalize + store (tf32-rounded) to [B, L, H*D]
    const int b_ = bh >> 4;
    const int h  = bh & (HEADS - 1);
    const float inv0 = 1.f / lrow0;
    const float inv1 = 1.f / lrow1;
    const int qrow = q0 + qr0;
    const size_t base0 = ((size_t)b_ * L_SEQ + qrow + g)     * CDIM + h * HD;
    const size_t base1 = ((size_t)b_ * L_SEQ + qrow + g + 8) * CDIM + h * HD;
#pragma unroll
    for (int nn = 0; nn < 8; nn++) {
        float2 v0 = make_float2(__uint_as_float(f2tf32(o[nn][0] * inv0)),
                                __uint_as_float(f2tf32(o[nn][1] * inv0)));
        float2 v1 = make_float2(__uint_as_float(f2tf32(o[nn][2] * inv1)),
                                __uint_as_float(f2tf32(o[nn][3] * inv1)));
        *(float2*)&att[base0 + nn * 8 + 2 * t] = v0;
        *(float2*)&att[base1 + nn * 8 + 2 * t] = v1;
    }
}

// ---------------------------------------------------------------------------
// Host launch
// ---------------------------------------------------------------------------
extern "C" void kernel_launch(void* const* d_in, const int* in_sizes, int n_in,
                              void* d_out, int out_size)
{
    const float* x       = (const float*)d_in[0];
    const float* w_qkv   = (const float*)d_in[1];
    const float* w_out   = (const float*)d_in[2];
    const float* q_scale = (const float*)d_in[3];
    const float* q_bias  = (const float*)d_in[4];
    const float* k_scale = (const float*)d_in[5];
    const float* k_bias  = (const float*)d_in[6];
    float* out = (float*)d_out;

    void *p_qkv, *p_q, *p_k, *p_v, *p_att, *p_xr, *p_wr, *p_wor;
    cudaGetSymbolAddress(&p_qkv, g_qkv);
    cudaGetSymbolAddress(&p_q, g_q);
    cudaGetSymbolAddress(&p_k, g_k);
    cudaGetSymbolAddress(&p_v, g_v);
    cudaGetSymbolAddress(&p_att, g_att);
    cudaGetSymbolAddress(&p_xr, g_xr);
    cudaGetSymbolAddress(&p_wr, g_wr);
    cudaGetSymbolAddress(&p_wor, g_wor);

    // 0) pre-round inputs to tf32
    {
        int n4x = MTOT * CDIM / 4;          // 1,048,576
        int n4w = CDIM * THREEC / 4;        // 786,432
        int n4o = CDIM * CDIM / 4;          // 262,144
        round_tf32_kernel<<<(n4x + 255) / 256, 256>>>(x, (float*)p_xr, n4x);
        round_tf32_kernel<<<(n4w + 255) / 256, 256>>>(w_qkv, (float*)p_wr, n4w);
        round_tf32_kernel<<<(n4o + 255) / 256, 256>>>(w_out, (float*)p_wor, n4o);
    }

    // 1) QKV projection
    cudaFuncSetAttribute(gemm_db_kernel, cudaFuncAttributeMaxDynamicSharedMemorySize,
                         GEMM_SMEM_BYTES);
    gemm_db_kernel<<<dim3(THREEC / 128, MTOT / 128), 256, GEMM_SMEM_BYTES>>>(
        (const float*)p_xr, (const float*)p_wr, (float*)p_qkv, MTOT, THREEC, CDIM);

    // 2) QK LayerNorm + head split
    ln_split_kernel<<<(MTOT * HEADS) / 8, 256>>>(
        (const float*)p_qkv, q_scale, q_bias, k_scale, k_bias,
        (float*)p_q, (float*)p_k, (float*)p_v);

    // 3) Flash attention
    cudaFuncSetAttribute(attn_mma_kernel, cudaFuncAttributeMaxDynamicSharedMemorySize,
                         ATTN_SMEM_BYTES);
    attn_mma_kernel<<<dim3(L_SEQ / 128, BATCH * HEADS), 256, ATTN_SMEM_BYTES>>>(
        (const float*)p_q, (const float*)p_k, (const float*)p_v, (float*)p_att);

    // 4) Output projection
    gemm_db_kernel<<<dim3(CDIM / 128, MTOT / 128), 256, GEMM_SMEM_BYTES>>>(
        (const float*)p_att, (const float*)p_wor, out, MTOT, CDIM, CDIM);
}